// round 11
// baseline (speedup 1.0000x reference)
#include <cuda_runtime.h>
#include <cuda_bf16.h>
#include <cuda_fp16.h>
#include <math.h>
#include <stdint.h>

#define N_NODES 50000
#define N_EDGES 800000
#define F 128
#define EPSW 1e-12f
#define ASTRIDE 264   // bf16 elems per SMEM row: 256 data + 8 pad (conflict-free)

#define SCAN_BLOCKS 50
#define SCAN_CHUNK  1000   // SCAN_BLOCKS * SCAN_CHUNK == N_NODES
#define FIX_SCALE 16777216.0f   // 2^24 fixed-point for packed wdeg

// ---------------- scratch (device globals; no allocation allowed) ----------
__device__ unsigned long long g_pack_out[N_NODES];  // (cnt<<32) | wdeg*2^24
__device__ unsigned long long g_pack_in [N_NODES];
__device__ float g_r_out   [N_NODES];    // rsqrt(wdeg_out)*rsqrt(cnt_out)
__device__ float g_r_in    [N_NODES];    // rsqrt(wdeg_in) *rsqrt(cnt_in)
__device__ int   g_row_start[N_NODES + 1];
__device__ int   g_cursor  [N_NODES];
__device__ int   g_blk_sum [SCAN_BLOCKS];
__device__ int2  g_csr     [N_EDGES];        // packed {src, coef bits}
__device__ __half g_x16    [(size_t)N_NODES * F];   // fp16 input features
__device__ __half g_h16    [(size_t)N_NODES * F];   // fp16 layer-1 activations
// B' = hi/lo-split transposed weights: [layer][n][k'] k'<128 = hi, k'>=128 = lo
__device__ __nv_bfloat16 g_bp[2 * 128 * 256];

// ---------------- helpers ---------------------------------------------------
__device__ __forceinline__ float selu_f(float v) {
    const float scale = 1.0507009873554805f;
    const float alpha = 1.6732632423543772f;
    return v > 0.0f ? scale * v : scale * alpha * expm1f(v);
}

__device__ __forceinline__ uint32_t pack_bf16x2(__nv_bfloat16 a, __nv_bfloat16 b) {
    return (uint32_t)__bfloat16_as_ushort(a) | ((uint32_t)__bfloat16_as_ushort(b) << 16);
}

__device__ __forceinline__ unsigned long long pack_deg(float w) {
    return (1ULL << 32) | (unsigned long long)__float2uint_rn(w * FIX_SCALE);
}

__device__ __forceinline__ void mma16816(float c[4], const uint32_t a[4],
                                         const uint32_t b[2]) {
    asm volatile(
        "mma.sync.aligned.m16n8k16.row.col.f32.bf16.bf16.f32 "
        "{%0,%1,%2,%3}, {%4,%5,%6,%7}, {%8,%9}, {%0,%1,%2,%3};"
        : "+f"(c[0]), "+f"(c[1]), "+f"(c[2]), "+f"(c[3])
        : "r"(a[0]), "r"(a[1]), "r"(a[2]), "r"(a[3]), "r"(b[0]), "r"(b[1]));
}

// ---------------- setup: prep_w + x2h + zero, fused ------------------------
__global__ void setup_kernel(const float* __restrict__ x,
                             const float* __restrict__ W1,
                             const float* __restrict__ W2) {
    int i = blockIdx.x * blockDim.x + threadIdx.x;

    // fp16 conversion of x (N*F/4 = 409600 float4 units)
    if (i < (N_NODES * F) / 4) {
        float4 v = *((const float4*)x + i);
        __half2 a = __floats2half2_rn(v.x, v.y);
        __half2 b = __floats2half2_rn(v.z, v.w);
        uint2 o;
        o.x = *(uint32_t*)&a;
        o.y = *(uint32_t*)&b;
        *((uint2*)g_x16 + i) = o;
    }
    // weight transpose + hi/lo split (16384 elements)
    if (i < 128 * 128) {
        int k = i >> 7, n = i & 127;
        #pragma unroll
        for (int layer = 0; layer < 2; layer++) {
            float v = (layer ? W2 : W1)[i];     // W[k][n]
            __nv_bfloat16 hi = __float2bfloat16(v);
            __nv_bfloat16 lo = __float2bfloat16(v - __bfloat162float(hi));
            g_bp[(size_t)layer * 32768 + n * 256 + k]       = hi;
            g_bp[(size_t)layer * 32768 + n * 256 + 128 + k] = lo;
        }
    }
    // zero packed degree accumulators
    if (i < N_NODES) {
        g_pack_out[i] = 0ULL;
        g_pack_in [i] = 0ULL;
    }
}

// ---------------- degrees: 2 packed 64-bit atomics per edge, x4 vector ------
__global__ void deg_kernel(const int* __restrict__ src,
                           const int* __restrict__ dst,
                           const float* __restrict__ w) {
    int e4 = (blockIdx.x * blockDim.x + threadIdx.x) * 4;
    if (e4 >= N_EDGES) return;     // N_EDGES % 4 == 0
    int4   s4 = *(const int4*)  (src + e4);
    int4   d4 = *(const int4*)  (dst + e4);
    float4 w4 = *(const float4*)(w   + e4);
    atomicAdd(&g_pack_out[s4.x], pack_deg(w4.x));
    atomicAdd(&g_pack_in [d4.x], pack_deg(w4.x));
    atomicAdd(&g_pack_out[s4.y], pack_deg(w4.y));
    atomicAdd(&g_pack_in [d4.y], pack_deg(w4.y));
    atomicAdd(&g_pack_out[s4.z], pack_deg(w4.z));
    atomicAdd(&g_pack_in [d4.z], pack_deg(w4.z));
    atomicAdd(&g_pack_out[s4.w], pack_deg(w4.w));
    atomicAdd(&g_pack_in [d4.w], pack_deg(w4.w));
}

// ---- scan stage 1 + node coefficients (fused; both node-wise) --------------
__global__ void scan1_kernel() {
    __shared__ int wsum[8];
    int b = blockIdx.x, t = threadIdx.x;       // 256 threads
    int base = b * SCAN_CHUNK;
    int local = 0;
    #pragma unroll
    for (int j = 0; j < 4; j++) {
        int i = t * 4 + j;
        if (i < SCAN_CHUNK) {
            int node = base + i;
            unsigned long long po = g_pack_out[node];
            unsigned long long pi = g_pack_in [node];
            float wo = (float)(unsigned)po * (1.0f / FIX_SCALE);
            float wi = (float)(unsigned)pi * (1.0f / FIX_SCALE);
            int co = (int)(po >> 32), ci = (int)(pi >> 32);
            g_r_out[node] = rsqrtf(fmaxf(wo, EPSW)) * rsqrtf(fmaxf((float)co, 1.0f));
            g_r_in [node] = rsqrtf(fmaxf(wi, EPSW)) * rsqrtf(fmaxf((float)ci, 1.0f));
            local += ci;
        }
    }
    int lane = t & 31, wid = t >> 5;
    #pragma unroll
    for (int off = 16; off > 0; off >>= 1)
        local += __shfl_down_sync(0xffffffff, local, off);
    if (lane == 0) wsum[wid] = local;
    __syncthreads();
    if (t == 0) {
        int s = 0;
        #pragma unroll
        for (int k = 0; k < 8; k++) s += wsum[k];
        g_blk_sum[b] = s;
    }
}

// ---- scan stage 2 (inline block-sum scan) + per-node exclusive scan --------
__global__ void scan3_kernel() {
    __shared__ int blk[SCAN_BLOCKS + 1];
    __shared__ int wsum[8];
    int b = blockIdx.x, t = threadIdx.x;       // 256 threads
    if (t == 0) {
        int run = 0;
        for (int k = 0; k < SCAN_BLOCKS; k++) {
            int c = g_blk_sum[k];
            blk[k] = run;
            run += c;
        }
        blk[SCAN_BLOCKS] = run;
    }
    __syncthreads();
    if (b == 0 && t == 0) g_row_start[N_NODES] = blk[SCAN_BLOCKS];

    int base = b * SCAN_CHUNK;
    int i0 = t * 4;
    int c0 = 0, c1 = 0, c2 = 0, c3 = 0;
    if (i0 < SCAN_CHUNK) {
        c0 = (int)(g_pack_in[base + i0]     >> 32);
        c1 = (int)(g_pack_in[base + i0 + 1] >> 32);
        c2 = (int)(g_pack_in[base + i0 + 2] >> 32);
        c3 = (int)(g_pack_in[base + i0 + 3] >> 32);
    }
    int s = c0 + c1 + c2 + c3;

    int lane = t & 31, wid = t >> 5;
    int incl = s;
    #pragma unroll
    for (int off = 1; off < 32; off <<= 1) {
        int n = __shfl_up_sync(0xffffffff, incl, off);
        if (lane >= off) incl += n;
    }
    if (lane == 31) wsum[wid] = incl;
    __syncthreads();
    int wpre = 0;
    #pragma unroll
    for (int k = 0; k < 8; k++) wpre += (k < wid) ? wsum[k] : 0;

    if (i0 < SCAN_CHUNK) {
        int run = blk[b] + wpre + (incl - s);
        g_row_start[base + i0]     = run;  g_cursor[base + i0]     = run;  run += c0;
        g_row_start[base + i0 + 1] = run;  g_cursor[base + i0 + 1] = run;  run += c1;
        g_row_start[base + i0 + 2] = run;  g_cursor[base + i0 + 2] = run;  run += c2;
        g_row_start[base + i0 + 3] = run;  g_cursor[base + i0 + 3] = run;
    }
}

// ---------------- scatter: x4 vectorized edge loads --------------------------
__global__ void scatter_kernel(const int* __restrict__ src,
                               const int* __restrict__ dst,
                               const float* __restrict__ w) {
    int e4 = (blockIdx.x * blockDim.x + threadIdx.x) * 4;
    if (e4 >= N_EDGES) return;
    int4   s4 = *(const int4*)  (src + e4);
    int4   d4 = *(const int4*)  (dst + e4);
    float4 w4 = *(const float4*)(w   + e4);

    float c0 = w4.x * g_r_out[s4.x] * g_r_in[d4.x];
    float c1 = w4.y * g_r_out[s4.y] * g_r_in[d4.y];
    float c2 = w4.z * g_r_out[s4.z] * g_r_in[d4.z];
    float c3 = w4.w * g_r_out[s4.w] * g_r_in[d4.w];

    int p0 = atomicAdd(&g_cursor[d4.x], 1);
    g_csr[p0] = make_int2(s4.x, __float_as_int(c0));
    int p1 = atomicAdd(&g_cursor[d4.y], 1);
    g_csr[p1] = make_int2(s4.y, __float_as_int(c1));
    int p2 = atomicAdd(&g_cursor[d4.z], 1);
    g_csr[p2] = make_int2(s4.z, __float_as_int(c2));
    int p3 = atomicAdd(&g_cursor[d4.w], 1);
    g_csr[p3] = make_int2(s4.w, __float_as_int(c3));
}

// ---------------- FUSED SpMM + GEMM:  out = selu( (A·feat) @ W + b ) ---------
// 512 threads / 16 warps per CTA; CTA owns 128 destination rows.
// Phase 1: load B' tile. Phase 2: each warp aggregates 8 CSR rows (fp32 regs),
// converts to bf16 hi/lo, writes straight into the sA SMEM tile (no g_agg).
// Phase 3: mma mainloop, warp tile 32x32, hi/lo split = 3 passes of K=128.
__global__ void __launch_bounds__(512, 1)
fused_layer_kernel(const float* __restrict__ bias, float* __restrict__ outp,
                   int layer) {
    extern __shared__ __nv_bfloat16 smem[];
    __nv_bfloat16* sA = smem;                         // [128][ASTRIDE]
    __nv_bfloat16* sB = smem + 128 * ASTRIDE;         // [128][ASTRIDE]

    int tid = threadIdx.x;
    int wid = tid >> 5, lane = tid & 31;
    int g = lane >> 2, tg = lane & 3;
    int bm = blockIdx.x * 128;

    const __half* feat = (layer == 0) ? g_x16 : g_h16;

    // ---- phase 1: load B' tile (pre-split [n][256] bf16); 4096 uint4 / 512 thr
    const __nv_bfloat16* bp = g_bp + (size_t)layer * 32768;
    #pragma unroll
    for (int it = 0; it < 8; it++) {
        int idx = it * 512 + tid;          // 0..4095 uint4 units
        int n  = idx >> 5;                 // 0..127
        int kp = (idx & 31) * 8;           // 0..248
        *(uint4*)(sB + n * ASTRIDE + kp) = *(const uint4*)(bp + (size_t)n * 256 + kp);
    }

    // ---- phase 2: SpMM for this CTA's 128 rows; warp handles 8 rows ---------
    for (int rr = 0; rr < 8; rr++) {
        int r = wid * 8 + rr;              // local row 0..127
        int node = bm + r;
        float acc0 = 0.f, acc1 = 0.f, acc2 = 0.f, acc3 = 0.f;
        if (node < N_NODES) {
            int beg = g_row_start[node];
            int end = g_row_start[node + 1];
            int i = beg;
            for (; i + 3 < end; i += 4) {
                int2 p0 = g_csr[i];
                int2 p1 = g_csr[i + 1];
                int2 p2 = g_csr[i + 2];
                int2 p3 = g_csr[i + 3];
                uint2 v0 = *((const uint2*)(feat + (size_t)p0.x * F) + lane);
                uint2 v1 = *((const uint2*)(feat + (size_t)p1.x * F) + lane);
                uint2 v2 = *((const uint2*)(feat + (size_t)p2.x * F) + lane);
                uint2 v3 = *((const uint2*)(feat + (size_t)p3.x * F) + lane);
                float c0 = __int_as_float(p0.y), c1 = __int_as_float(p1.y);
                float c2 = __int_as_float(p2.y), c3 = __int_as_float(p3.y);
                {
                    float2 a = __half22float2(*(__half2*)&v0.x);
                    float2 b = __half22float2(*(__half2*)&v0.y);
                    acc0 = fmaf(c0, a.x, acc0); acc1 = fmaf(c0, a.y, acc1);
                    acc2 = fmaf(c0, b.x, acc2); acc3 = fmaf(c0, b.y, acc3);
                }
                {
                    float2 a = __half22float2(*(__half2*)&v1.x);
                    float2 b = __half22float2(*(__half2*)&v1.y);
                    acc0 = fmaf(c1, a.x, acc0); acc1 = fmaf(c1, a.y, acc1);
                    acc2 = fmaf(c1, b.x, acc2); acc3 = fmaf(c1, b.y, acc3);
                }
                {
                    float2 a = __half22float2(*(__half2*)&v2.x);
                    float2 b = __half22float2(*(__half2*)&v2.y);
                    acc0 = fmaf(c2, a.x, acc0); acc1 = fmaf(c2, a.y, acc1);
                    acc2 = fmaf(c2, b.x, acc2); acc3 = fmaf(c2, b.y, acc3);
                }
                {
                    float2 a = __half22float2(*(__half2*)&v3.x);
                    float2 b = __half22float2(*(__half2*)&v3.y);
                    acc0 = fmaf(c3, a.x, acc0); acc1 = fmaf(c3, a.y, acc1);
                    acc2 = fmaf(c3, b.x, acc2); acc3 = fmaf(c3, b.y, acc3);
                }
            }
            for (; i < end; i++) {
                int2 p = g_csr[i];
                float c = __int_as_float(p.y);
                uint2 v = *((const uint2*)(feat + (size_t)p.x * F) + lane);
                float2 a = __half22float2(*(__half2*)&v.x);
                float2 b = __half22float2(*(__half2*)&v.y);
                acc0 = fmaf(c, a.x, acc0); acc1 = fmaf(c, a.y, acc1);
                acc2 = fmaf(c, b.x, acc2); acc3 = fmaf(c, b.y, acc3);
            }
        }
        // fp32 -> bf16 hi|lo, straight into sA (lane owns features lane*4..+3)
        __nv_bfloat16 h0 = __float2bfloat16(acc0);
        __nv_bfloat16 h1 = __float2bfloat16(acc1);
        __nv_bfloat16 h2 = __float2bfloat16(acc2);
        __nv_bfloat16 h3 = __float2bfloat16(acc3);
        __nv_bfloat16 l0 = __float2bfloat16(acc0 - __bfloat162float(h0));
        __nv_bfloat16 l1 = __float2bfloat16(acc1 - __bfloat162float(h1));
        __nv_bfloat16 l2 = __float2bfloat16(acc2 - __bfloat162float(h2));
        __nv_bfloat16 l3 = __float2bfloat16(acc3 - __bfloat162float(h3));
        uint2 hi2, lo2;
        hi2.x = pack_bf16x2(h0, h1); hi2.y = pack_bf16x2(h2, h3);
        lo2.x = pack_bf16x2(l0, l1); lo2.y = pack_bf16x2(l2, l3);
        *(uint2*)(sA + r * ASTRIDE + lane * 4)       = hi2;
        *(uint2*)(sA + r * ASTRIDE + 128 + lane * 4) = lo2;
    }
    __syncthreads();

    // ---- phase 3: mma mainloop; 16 warps, warp tile 32(m) x 32(n) -----------
    int warp_m = (wid & 3) * 32;
    int warp_n = (wid >> 2) * 32;

    float c[2][4][4];
    #pragma unroll
    for (int mt = 0; mt < 2; mt++)
        #pragma unroll
        for (int nt = 0; nt < 4; nt++)
            #pragma unroll
            for (int q = 0; q < 4; q++) c[mt][nt][q] = 0.0f;

    #pragma unroll
    for (int pass = 0; pass < 3; pass++) {
        int aoff = (pass == 1) ? 128 : 0;
        int boff = (pass == 2) ? 128 : 0;
        #pragma unroll
        for (int k0 = 0; k0 < 128; k0 += 16) {
            uint32_t a[2][4], b[4][2];
            #pragma unroll
            for (int mt = 0; mt < 2; mt++) {
                const __nv_bfloat16* base =
                    sA + (warp_m + mt * 16 + g) * ASTRIDE + aoff + k0 + 2 * tg;
                a[mt][0] = *(const uint32_t*)(base);
                a[mt][1] = *(const uint32_t*)(base + 8 * ASTRIDE);
                a[mt][2] = *(const uint32_t*)(base + 8);
                a[mt][3] = *(const uint32_t*)(base + 8 * ASTRIDE + 8);
            }
            #pragma unroll
            for (int nt = 0; nt < 4; nt++) {
                const __nv_bfloat16* base =
                    sB + (warp_n + nt * 8 + g) * ASTRIDE + boff + k0 + 2 * tg;
                b[nt][0] = *(const uint32_t*)(base);
                b[nt][1] = *(const uint32_t*)(base + 8);
            }
            #pragma unroll
            for (int mt = 0; mt < 2; mt++)
                #pragma unroll
                for (int nt = 0; nt < 4; nt++)
                    mma16816(c[mt][nt], a[mt], b[nt]);
        }
    }

    // ---- epilogue: bias + selu; layer 0 -> fp16 g_h16, layer 1 -> fp32 out --
    #pragma unroll
    for (int nt = 0; nt < 4; nt++) {
        int col = warp_n + nt * 8 + 2 * tg;
        float b0 = bias[col], b1 = bias[col + 1];
        #pragma unroll
        for (int mt = 0; mt < 2; mt++) {
            int row0 = bm + warp_m + mt * 16 + g;
            int row1 = row0 + 8;
            if (layer == 0) {
                if (row0 < N_NODES) {
                    __half2 o = __floats2half2_rn(selu_f(c[mt][nt][0] + b0),
                                                  selu_f(c[mt][nt][1] + b1));
                    *(__half2*)(g_h16 + (size_t)row0 * F + col) = o;
                }
                if (row1 < N_NODES) {
                    __half2 o = __floats2half2_rn(selu_f(c[mt][nt][2] + b0),
                                                  selu_f(c[mt][nt][3] + b1));
                    *(__half2*)(g_h16 + (size_t)row1 * F + col) = o;
                }
            } else {
                if (row0 < N_NODES) {
                    float2 o;
                    o.x = selu_f(c[mt][nt][0] + b0);
                    o.y = selu_f(c[mt][nt][1] + b1);
                    *(float2*)(outp + (size_t)row0 * F + col) = o;
                }
                if (row1 < N_NODES) {
                    float2 o;
                    o.x = selu_f(c[mt][nt][2] + b0);
                    o.y = selu_f(c[mt][nt][3] + b1);
                    *(float2*)(outp + (size_t)row1 * F + col) = o;
                }
            }
        }
    }
}

// ---------------- launch ------------------------------------------------------
extern "C" void kernel_launch(void* const* d_in, const int* in_sizes, int n_in,
                              void* d_out, int out_size) {
    const float* x   = (const float*)d_in[0];
    const int*   src = (const int*)  d_in[1];
    const int*   dst = (const int*)  d_in[2];
    const float* ew  = (const float*)d_in[3];
    const float* W1  = (const float*)d_in[4];
    const float* b1  = (const float*)d_in[5];
    const float* W2  = (const float*)d_in[6];
    const float* b2  = (const float*)d_in[7];
    float* out = (float*)d_out;

    const int TB = 256;
    dim3 setupGrid((N_NODES * F / 4 + TB - 1) / TB);
    dim3 edge4Grid((N_EDGES / 4 + TB - 1) / TB);
    dim3 fusedGrid((N_NODES + 127) / 128);
    const int FUSED_SMEM = 2 * 128 * ASTRIDE * 2;   // 135168 B

    cudaFuncSetAttribute(fused_layer_kernel,
                         cudaFuncAttributeMaxDynamicSharedMemorySize, FUSED_SMEM);

    // 0: setup (fp16 features + weight split + zero degree accumulators)
    setup_kernel<<<setupGrid, TB>>>(x, W1, W2);
    // 1: packed degrees (2 atomics/edge)
    deg_kernel<<<edge4Grid, TB>>>(src, dst, ew);
    // 2: block sums + node coefficients
    scan1_kernel<<<SCAN_BLOCKS, 256>>>();
    // 3: full exclusive scan -> row_start / cursor
    scan3_kernel<<<SCAN_BLOCKS, 256>>>();
    // 4: scatter edges into CSR
    scatter_kernel<<<edge4Grid, TB>>>(src, dst, ew);

    // 5: layer 1 (SpMM + GEMM fused)
    fused_layer_kernel<<<fusedGrid, 512, FUSED_SMEM>>>(b1, out, 0);
    // 6: layer 2
    fused_layer_kernel<<<fusedGrid, 512, FUSED_SMEM>>>(b2, out, 1);
}

// round 12
// speedup vs baseline: 1.4336x; 1.4336x over previous
#include <cuda_runtime.h>
#include <cuda_bf16.h>
#include <cuda_fp16.h>
#include <math.h>
#include <stdint.h>

#define N_NODES 50000
#define N_EDGES 800000
#define F 128
#define EPSW 1e-12f
#define ASTRIDE 264   // bf16 elems per SMEM row: 256 data + 8 pad (conflict-free)
#define MTILE 64      // rows per fused CTA (2 CTAs/SM)

#define SCAN_BLOCKS 50
#define SCAN_CHUNK  1000   // SCAN_BLOCKS * SCAN_CHUNK == N_NODES
#define FIX_SCALE 16777216.0f   // 2^24 fixed-point for packed wdeg

// ---------------- scratch (device globals; no allocation allowed) ----------
__device__ unsigned long long g_pack_out[N_NODES];  // (cnt<<32) | wdeg*2^24
__device__ unsigned long long g_pack_in [N_NODES];
__device__ float g_r_out   [N_NODES];    // rsqrt(wdeg_out)*rsqrt(cnt_out)
__device__ float g_r_in    [N_NODES];    // rsqrt(wdeg_in) *rsqrt(cnt_in)
__device__ int   g_row_start[N_NODES + 1];
__device__ int   g_cursor  [N_NODES];
__device__ int   g_blk_sum [SCAN_BLOCKS];
__device__ int2  g_csr     [N_EDGES];        // packed {src, coef bits}
__device__ __half g_x16    [(size_t)N_NODES * F];   // fp16 input features
__device__ __half g_h16    [(size_t)N_NODES * F];   // fp16 layer-1 activations
// B' = hi/lo-split transposed weights: [layer][n][k'] k'<128 = hi, k'>=128 = lo
__device__ __nv_bfloat16 g_bp[2 * 128 * 256];

// ---------------- helpers ---------------------------------------------------
__device__ __forceinline__ float selu_f(float v) {
    const float scale = 1.0507009873554805f;
    const float alpha = 1.6732632423543772f;
    return v > 0.0f ? scale * v : scale * alpha * expm1f(v);
}

__device__ __forceinline__ uint32_t pack_bf16x2(__nv_bfloat16 a, __nv_bfloat16 b) {
    return (uint32_t)__bfloat16_as_ushort(a) | ((uint32_t)__bfloat16_as_ushort(b) << 16);
}

__device__ __forceinline__ unsigned long long pack_deg(float w) {
    return (1ULL << 32) | (unsigned long long)__float2uint_rn(w * FIX_SCALE);
}

__device__ __forceinline__ void mma16816(float c[4], const uint32_t a[4],
                                         const uint32_t b[2]) {
    asm volatile(
        "mma.sync.aligned.m16n8k16.row.col.f32.bf16.bf16.f32 "
        "{%0,%1,%2,%3}, {%4,%5,%6,%7}, {%8,%9}, {%0,%1,%2,%3};"
        : "+f"(c[0]), "+f"(c[1]), "+f"(c[2]), "+f"(c[3])
        : "r"(a[0]), "r"(a[1]), "r"(a[2]), "r"(a[3]), "r"(b[0]), "r"(b[1]));
}

// ---------------- setup: prep_w + x2h + zero, fused ------------------------
__global__ void setup_kernel(const float* __restrict__ x,
                             const float* __restrict__ W1,
                             const float* __restrict__ W2) {
    int i = blockIdx.x * blockDim.x + threadIdx.x;

    if (i < (N_NODES * F) / 4) {
        float4 v = *((const float4*)x + i);
        __half2 a = __floats2half2_rn(v.x, v.y);
        __half2 b = __floats2half2_rn(v.z, v.w);
        uint2 o;
        o.x = *(uint32_t*)&a;
        o.y = *(uint32_t*)&b;
        *((uint2*)g_x16 + i) = o;
    }
    if (i < 128 * 128) {
        int k = i >> 7, n = i & 127;
        #pragma unroll
        for (int layer = 0; layer < 2; layer++) {
            float v = (layer ? W2 : W1)[i];     // W[k][n]
            __nv_bfloat16 hi = __float2bfloat16(v);
            __nv_bfloat16 lo = __float2bfloat16(v - __bfloat162float(hi));
            g_bp[(size_t)layer * 32768 + n * 256 + k]       = hi;
            g_bp[(size_t)layer * 32768 + n * 256 + 128 + k] = lo;
        }
    }
    if (i < N_NODES) {
        g_pack_out[i] = 0ULL;
        g_pack_in [i] = 0ULL;
    }
}

// ---------------- degrees: 2 packed 64-bit atomics per edge, x4 vector ------
__global__ void deg_kernel(const int* __restrict__ src,
                           const int* __restrict__ dst,
                           const float* __restrict__ w) {
    int e4 = (blockIdx.x * blockDim.x + threadIdx.x) * 4;
    if (e4 >= N_EDGES) return;     // N_EDGES % 4 == 0
    int4   s4 = *(const int4*)  (src + e4);
    int4   d4 = *(const int4*)  (dst + e4);
    float4 w4 = *(const float4*)(w   + e4);
    atomicAdd(&g_pack_out[s4.x], pack_deg(w4.x));
    atomicAdd(&g_pack_in [d4.x], pack_deg(w4.x));
    atomicAdd(&g_pack_out[s4.y], pack_deg(w4.y));
    atomicAdd(&g_pack_in [d4.y], pack_deg(w4.y));
    atomicAdd(&g_pack_out[s4.z], pack_deg(w4.z));
    atomicAdd(&g_pack_in [d4.z], pack_deg(w4.z));
    atomicAdd(&g_pack_out[s4.w], pack_deg(w4.w));
    atomicAdd(&g_pack_in [d4.w], pack_deg(w4.w));
}

// ---- scan stage 1 + node coefficients (fused; both node-wise) --------------
__global__ void scan1_kernel() {
    __shared__ int wsum[8];
    int b = blockIdx.x, t = threadIdx.x;       // 256 threads
    int base = b * SCAN_CHUNK;
    int local = 0;
    #pragma unroll
    for (int j = 0; j < 4; j++) {
        int i = t * 4 + j;
        if (i < SCAN_CHUNK) {
            int node = base + i;
            unsigned long long po = g_pack_out[node];
            unsigned long long pi = g_pack_in [node];
            float wo = (float)(unsigned)po * (1.0f / FIX_SCALE);
            float wi = (float)(unsigned)pi * (1.0f / FIX_SCALE);
            int co = (int)(po >> 32), ci = (int)(pi >> 32);
            g_r_out[node] = rsqrtf(fmaxf(wo, EPSW)) * rsqrtf(fmaxf((float)co, 1.0f));
            g_r_in [node] = rsqrtf(fmaxf(wi, EPSW)) * rsqrtf(fmaxf((float)ci, 1.0f));
            local += ci;
        }
    }
    int lane = t & 31, wid = t >> 5;
    #pragma unroll
    for (int off = 16; off > 0; off >>= 1)
        local += __shfl_down_sync(0xffffffff, local, off);
    if (lane == 0) wsum[wid] = local;
    __syncthreads();
    if (t == 0) {
        int s = 0;
        #pragma unroll
        for (int k = 0; k < 8; k++) s += wsum[k];
        g_blk_sum[b] = s;
    }
}

// ---- scan stage 2 (inline block-sum scan) + per-node exclusive scan --------
__global__ void scan3_kernel() {
    __shared__ int blk[SCAN_BLOCKS + 1];
    __shared__ int wsum[8];
    int b = blockIdx.x, t = threadIdx.x;       // 256 threads
    if (t == 0) {
        int run = 0;
        for (int k = 0; k < SCAN_BLOCKS; k++) {
            int c = g_blk_sum[k];
            blk[k] = run;
            run += c;
        }
        blk[SCAN_BLOCKS] = run;
    }
    __syncthreads();
    if (b == 0 && t == 0) g_row_start[N_NODES] = blk[SCAN_BLOCKS];

    int base = b * SCAN_CHUNK;
    int i0 = t * 4;
    int c0 = 0, c1 = 0, c2 = 0, c3 = 0;
    if (i0 < SCAN_CHUNK) {
        c0 = (int)(g_pack_in[base + i0]     >> 32);
        c1 = (int)(g_pack_in[base + i0 + 1] >> 32);
        c2 = (int)(g_pack_in[base + i0 + 2] >> 32);
        c3 = (int)(g_pack_in[base + i0 + 3] >> 32);
    }
    int s = c0 + c1 + c2 + c3;

    int lane = t & 31, wid = t >> 5;
    int incl = s;
    #pragma unroll
    for (int off = 1; off < 32; off <<= 1) {
        int n = __shfl_up_sync(0xffffffff, incl, off);
        if (lane >= off) incl += n;
    }
    if (lane == 31) wsum[wid] = incl;
    __syncthreads();
    int wpre = 0;
    #pragma unroll
    for (int k = 0; k < 8; k++) wpre += (k < wid) ? wsum[k] : 0;

    if (i0 < SCAN_CHUNK) {
        int run = blk[b] + wpre + (incl - s);
        g_row_start[base + i0]     = run;  g_cursor[base + i0]     = run;  run += c0;
        g_row_start[base + i0 + 1] = run;  g_cursor[base + i0 + 1] = run;  run += c1;
        g_row_start[base + i0 + 2] = run;  g_cursor[base + i0 + 2] = run;  run += c2;
        g_row_start[base + i0 + 3] = run;  g_cursor[base + i0 + 3] = run;
    }
}

// ---------------- scatter: x4 vectorized edge loads --------------------------
__global__ void scatter_kernel(const int* __restrict__ src,
                               const int* __restrict__ dst,
                               const float* __restrict__ w) {
    int e4 = (blockIdx.x * blockDim.x + threadIdx.x) * 4;
    if (e4 >= N_EDGES) return;
    int4   s4 = *(const int4*)  (src + e4);
    int4   d4 = *(const int4*)  (dst + e4);
    float4 w4 = *(const float4*)(w   + e4);

    float c0 = w4.x * g_r_out[s4.x] * g_r_in[d4.x];
    float c1 = w4.y * g_r_out[s4.y] * g_r_in[d4.y];
    float c2 = w4.z * g_r_out[s4.z] * g_r_in[d4.z];
    float c3 = w4.w * g_r_out[s4.w] * g_r_in[d4.w];

    int p0 = atomicAdd(&g_cursor[d4.x], 1);
    g_csr[p0] = make_int2(s4.x, __float_as_int(c0));
    int p1 = atomicAdd(&g_cursor[d4.y], 1);
    g_csr[p1] = make_int2(s4.y, __float_as_int(c1));
    int p2 = atomicAdd(&g_cursor[d4.z], 1);
    g_csr[p2] = make_int2(s4.z, __float_as_int(c2));
    int p3 = atomicAdd(&g_cursor[d4.w], 1);
    g_csr[p3] = make_int2(s4.w, __float_as_int(c3));
}

// ---------------- FUSED SpMM + GEMM, 64-row tiles, 2 CTAs/SM ----------------
// 512 threads / 16 warps; CTA owns 64 destination rows (warp: 4 rows).
// SMEM: sA 64x264 bf16 (33.8KB) + sB 128x264 bf16 (67.6KB) = 101KB -> 2 CTA/SM
// => 32 warps/SM during the gather phase (matches standalone SpMM occupancy),
// and one CTA's MMA overlaps the other's gathers.
__global__ void __launch_bounds__(512, 2)
fused_layer_kernel(const float* __restrict__ bias, float* __restrict__ outp,
                   int layer) {
    extern __shared__ __nv_bfloat16 smem[];
    __nv_bfloat16* sA = smem;                          // [MTILE][ASTRIDE]
    __nv_bfloat16* sB = smem + MTILE * ASTRIDE;        // [128][ASTRIDE]

    int tid = threadIdx.x;
    int wid = tid >> 5, lane = tid & 31;
    int g = lane >> 2, tg = lane & 3;
    int bm = blockIdx.x * MTILE;

    const __half* feat = (layer == 0) ? g_x16 : g_h16;

    // ---- phase 1: load B' tile (pre-split [n][256] bf16); 4096 uint4 --------
    const __nv_bfloat16* bp = g_bp + (size_t)layer * 32768;
    #pragma unroll
    for (int it = 0; it < 8; it++) {
        int idx = it * 512 + tid;          // 0..4095 uint4 units
        int n  = idx >> 5;                 // 0..127
        int kp = (idx & 31) * 8;           // 0..248
        *(uint4*)(sB + n * ASTRIDE + kp) = *(const uint4*)(bp + (size_t)n * 256 + kp);
    }

    // ---- phase 2: SpMM for this CTA's 64 rows; warp handles 4 rows ----------
    for (int rr = 0; rr < 4; rr++) {
        int r = wid * 4 + rr;              // local row 0..63
        int node = bm + r;
        float acc0 = 0.f, acc1 = 0.f, acc2 = 0.f, acc3 = 0.f;
        if (node < N_NODES) {
            int beg = g_row_start[node];
            int end = g_row_start[node + 1];
            int i = beg;
            for (; i + 1 < end; i += 2) {
                int2 p0 = g_csr[i];
                int2 p1 = g_csr[i + 1];
                uint2 v0 = *((const uint2*)(feat + (size_t)p0.x * F) + lane);
                uint2 v1 = *((const uint2*)(feat + (size_t)p1.x * F) + lane);
                float c0 = __int_as_float(p0.y), c1 = __int_as_float(p1.y);
                {
                    float2 a = __half22float2(*(__half2*)&v0.x);
                    float2 b = __half22float2(*(__half2*)&v0.y);
                    acc0 = fmaf(c0, a.x, acc0); acc1 = fmaf(c0, a.y, acc1);
                    acc2 = fmaf(c0, b.x, acc2); acc3 = fmaf(c0, b.y, acc3);
                }
                {
                    float2 a = __half22float2(*(__half2*)&v1.x);
                    float2 b = __half22float2(*(__half2*)&v1.y);
                    acc0 = fmaf(c1, a.x, acc0); acc1 = fmaf(c1, a.y, acc1);
                    acc2 = fmaf(c1, b.x, acc2); acc3 = fmaf(c1, b.y, acc3);
                }
            }
            if (i < end) {
                int2 p = g_csr[i];
                float c = __int_as_float(p.y);
                uint2 v = *((const uint2*)(feat + (size_t)p.x * F) + lane);
                float2 a = __half22float2(*(__half2*)&v.x);
                float2 b = __half22float2(*(__half2*)&v.y);
                acc0 = fmaf(c, a.x, acc0); acc1 = fmaf(c, a.y, acc1);
                acc2 = fmaf(c, b.x, acc2); acc3 = fmaf(c, b.y, acc3);
            }
        }
        // fp32 -> bf16 hi|lo, straight into sA (lane owns features lane*4..+3)
        __nv_bfloat16 h0 = __float2bfloat16(acc0);
        __nv_bfloat16 h1 = __float2bfloat16(acc1);
        __nv_bfloat16 h2 = __float2bfloat16(acc2);
        __nv_bfloat16 h3 = __float2bfloat16(acc3);
        __nv_bfloat16 l0 = __float2bfloat16(acc0 - __bfloat162float(h0));
        __nv_bfloat16 l1 = __float2bfloat16(acc1 - __bfloat162float(h1));
        __nv_bfloat16 l2 = __float2bfloat16(acc2 - __bfloat162float(h2));
        __nv_bfloat16 l3 = __float2bfloat16(acc3 - __bfloat162float(h3));
        uint2 hi2, lo2;
        hi2.x = pack_bf16x2(h0, h1); hi2.y = pack_bf16x2(h2, h3);
        lo2.x = pack_bf16x2(l0, l1); lo2.y = pack_bf16x2(l2, l3);
        *(uint2*)(sA + r * ASTRIDE + lane * 4)       = hi2;
        *(uint2*)(sA + r * ASTRIDE + 128 + lane * 4) = lo2;
    }
    __syncthreads();

    // ---- phase 3: mma mainloop; warp tile 32(m) x 16(n) ---------------------
    int warp_m = (wid & 1) * 32;       // 2 m-groups cover 64 rows
    int warp_n = (wid >> 1) * 16;      // 8 n-groups cover 128 cols

    float c[2][2][4];
    #pragma unroll
    for (int mt = 0; mt < 2; mt++)
        #pragma unroll
        for (int nt = 0; nt < 2; nt++)
            #pragma unroll
            for (int q = 0; q < 4; q++) c[mt][nt][q] = 0.0f;

    #pragma unroll
    for (int pass = 0; pass < 3; pass++) {
        int aoff = (pass == 1) ? 128 : 0;
        int boff = (pass == 2) ? 128 : 0;
        #pragma unroll
        for (int k0 = 0; k0 < 128; k0 += 16) {
            uint32_t a[2][4], b[2][2];
            #pragma unroll
            for (int mt = 0; mt < 2; mt++) {
                const __nv_bfloat16* base =
                    sA + (warp_m + mt * 16 + g) * ASTRIDE + aoff + k0 + 2 * tg;
                a[mt][0] = *(const uint32_t*)(base);
                a[mt][1] = *(const uint32_t*)(base + 8 * ASTRIDE);
                a[mt][2] = *(const uint32_t*)(base + 8);
                a[mt][3] = *(const uint32_t*)(base + 8 * ASTRIDE + 8);
            }
            #pragma unroll
            for (int nt = 0; nt < 2; nt++) {
                const __nv_bfloat16* base =
                    sB + (warp_n + nt * 8 + g) * ASTRIDE + boff + k0 + 2 * tg;
                b[nt][0] = *(const uint32_t*)(base);
                b[nt][1] = *(const uint32_t*)(base + 8);
            }
            #pragma unroll
            for (int mt = 0; mt < 2; mt++)
                #pragma unroll
                for (int nt = 0; nt < 2; nt++)
                    mma16816(c[mt][nt], a[mt], b[nt]);
        }
    }

    // ---- epilogue: bias + selu; layer 0 -> fp16 g_h16, layer 1 -> fp32 out --
    #pragma unroll
    for (int nt = 0; nt < 2; nt++) {
        int col = warp_n + nt * 8 + 2 * tg;
        float b0 = bias[col], b1 = bias[col + 1];
        #pragma unroll
        for (int mt = 0; mt < 2; mt++) {
            int row0 = bm + warp_m + mt * 16 + g;
            int row1 = row0 + 8;
            if (layer == 0) {
                if (row0 < N_NODES) {
                    __half2 o = __floats2half2_rn(selu_f(c[mt][nt][0] + b0),
                                                  selu_f(c[mt][nt][1] + b1));
                    *(__half2*)(g_h16 + (size_t)row0 * F + col) = o;
                }
                if (row1 < N_NODES) {
                    __half2 o = __floats2half2_rn(selu_f(c[mt][nt][2] + b0),
                                                  selu_f(c[mt][nt][3] + b1));
                    *(__half2*)(g_h16 + (size_t)row1 * F + col) = o;
                }
            } else {
                if (row0 < N_NODES) {
                    float2 o;
                    o.x = selu_f(c[mt][nt][0] + b0);
                    o.y = selu_f(c[mt][nt][1] + b1);
                    *(float2*)(outp + (size_t)row0 * F + col) = o;
                }
                if (row1 < N_NODES) {
                    float2 o;
                    o.x = selu_f(c[mt][nt][2] + b0);
                    o.y = selu_f(c[mt][nt][3] + b1);
                    *(float2*)(outp + (size_t)row1 * F + col) = o;
                }
            }
        }
    }
}

// ---------------- launch ------------------------------------------------------
extern "C" void kernel_launch(void* const* d_in, const int* in_sizes, int n_in,
                              void* d_out, int out_size) {
    const float* x   = (const float*)d_in[0];
    const int*   src = (const int*)  d_in[1];
    const int*   dst = (const int*)  d_in[2];
    const float* ew  = (const float*)d_in[3];
    const float* W1  = (const float*)d_in[4];
    const float* b1  = (const float*)d_in[5];
    const float* W2  = (const float*)d_in[6];
    const float* b2  = (const float*)d_in[7];
    float* out = (float*)d_out;

    const int TB = 256;
    dim3 setupGrid((N_NODES * F / 4 + TB - 1) / TB);
    dim3 edge4Grid((N_EDGES / 4 + TB - 1) / TB);
    dim3 fusedGrid((N_NODES + MTILE - 1) / MTILE);      // 782
    const int FUSED_SMEM = (MTILE + 128) * ASTRIDE * 2; // 101376 B

    cudaFuncSetAttribute(fused_layer_kernel,
                         cudaFuncAttributeMaxDynamicSharedMemorySize, FUSED_SMEM);

    // 0: setup (fp16 features + weight split + zero degree accumulators)
    setup_kernel<<<setupGrid, TB>>>(x, W1, W2);
    // 1: packed degrees (2 atomics/edge)
    deg_kernel<<<edge4Grid, TB>>>(src, dst, ew);
    // 2: block sums + node coefficients
    scan1_kernel<<<SCAN_BLOCKS, 256>>>();
    // 3: full exclusive scan -> row_start / cursor
    scan3_kernel<<<SCAN_BLOCKS, 256>>>();
    // 4: scatter edges into CSR
    scatter_kernel<<<edge4Grid, TB>>>(src, dst, ew);

    // 5: layer 1 (SpMM + GEMM fused, 2 CTAs/SM)
    fused_layer_kernel<<<fusedGrid, 512, FUSED_SMEM>>>(b1, out, 0);
    // 6: layer 2
    fused_layer_kernel<<<fusedGrid, 512, FUSED_SMEM>>>(b2, out, 1);
}

// round 13
// speedup vs baseline: 1.5579x; 1.0866x over previous
#include <cuda_runtime.h>
#include <cuda_bf16.h>
#include <cuda_fp16.h>
#include <math.h>
#include <stdint.h>

#define N_NODES 50000
#define N_EDGES 800000
#define F 128
#define EPSW 1e-12f
#define ASTRIDE 264   // bf16 elems per SMEM row: 256 data + 8 pad (conflict-free)
#define MTILE 64      // GEMM M-tile rows (2 CTAs/SM)

#define SCAN_BLOCKS 50
#define SCAN_CHUNK  1000   // SCAN_BLOCKS * SCAN_CHUNK == N_NODES
#define FIX_SCALE 16777216.0f   // 2^24 fixed-point for packed wdeg

// ---------------- scratch (device globals; no allocation allowed) ----------
__device__ unsigned long long g_pack_out[N_NODES];  // (cnt<<32) | wdeg*2^24
__device__ unsigned long long g_pack_in [N_NODES];
__device__ float g_r_out   [N_NODES];    // rsqrt(wdeg_out)*rsqrt(cnt_out)
__device__ float g_r_in    [N_NODES];    // rsqrt(wdeg_in) *rsqrt(cnt_in)
__device__ int   g_row_start[N_NODES + 1];
__device__ int   g_cursor  [N_NODES];
__device__ int   g_blk_sum [SCAN_BLOCKS];
__device__ int2  g_csr     [N_EDGES];        // packed {src, coef bits}
__device__ float g_agg     [(size_t)N_NODES * F];
__device__ __half g_x16    [(size_t)N_NODES * F];   // fp16 input features
__device__ __half g_h16    [(size_t)N_NODES * F];   // fp16 layer-1 activations
// B' = hi/lo-split transposed weights: [layer][n][k'] k'<128 = hi, k'>=128 = lo
__device__ __nv_bfloat16 g_bp[2 * 128 * 256];

// ---------------- helpers ---------------------------------------------------
__device__ __forceinline__ float selu_f(float v) {
    const float scale = 1.0507009873554805f;
    const float alpha = 1.6732632423543772f;
    return v > 0.0f ? scale * v : scale * alpha * expm1f(v);
}

__device__ __forceinline__ uint32_t pack_bf16x2(__nv_bfloat16 a, __nv_bfloat16 b) {
    return (uint32_t)__bfloat16_as_ushort(a) | ((uint32_t)__bfloat16_as_ushort(b) << 16);
}

__device__ __forceinline__ unsigned long long pack_deg(float w) {
    return (1ULL << 32) | (unsigned long long)__float2uint_rn(w * FIX_SCALE);
}

__device__ __forceinline__ void mma16816(float c[4], const uint32_t a[4],
                                         const uint32_t b[2]) {
    asm volatile(
        "mma.sync.aligned.m16n8k16.row.col.f32.bf16.bf16.f32 "
        "{%0,%1,%2,%3}, {%4,%5,%6,%7}, {%8,%9}, {%0,%1,%2,%3};"
        : "+f"(c[0]), "+f"(c[1]), "+f"(c[2]), "+f"(c[3])
        : "r"(a[0]), "r"(a[1]), "r"(a[2]), "r"(a[3]), "r"(b[0]), "r"(b[1]));
}

// ---------------- setup: prep_w + x2h + zero, fused ------------------------
__global__ void setup_kernel(const float* __restrict__ x,
                             const float* __restrict__ W1,
                             const float* __restrict__ W2) {
    int i = blockIdx.x * blockDim.x + threadIdx.x;

    if (i < (N_NODES * F) / 4) {
        float4 v = *((const float4*)x + i);
        __half2 a = __floats2half2_rn(v.x, v.y);
        __half2 b = __floats2half2_rn(v.z, v.w);
        uint2 o;
        o.x = *(uint32_t*)&a;
        o.y = *(uint32_t*)&b;
        *((uint2*)g_x16 + i) = o;
    }
    if (i < 128 * 128) {
        int k = i >> 7, n = i & 127;
        #pragma unroll
        for (int layer = 0; layer < 2; layer++) {
            float v = (layer ? W2 : W1)[i];     // W[k][n]
            __nv_bfloat16 hi = __float2bfloat16(v);
            __nv_bfloat16 lo = __float2bfloat16(v - __bfloat162float(hi));
            g_bp[(size_t)layer * 32768 + n * 256 + k]       = hi;
            g_bp[(size_t)layer * 32768 + n * 256 + 128 + k] = lo;
        }
    }
    if (i < N_NODES) {
        g_pack_out[i] = 0ULL;
        g_pack_in [i] = 0ULL;
    }
}

// ---------------- degrees: 2 packed 64-bit atomics per edge, x4 vector ------
__global__ void deg_kernel(const int* __restrict__ src,
                           const int* __restrict__ dst,
                           const float* __restrict__ w) {
    int e4 = (blockIdx.x * blockDim.x + threadIdx.x) * 4;
    if (e4 >= N_EDGES) return;     // N_EDGES % 4 == 0
    int4   s4 = *(const int4*)  (src + e4);
    int4   d4 = *(const int4*)  (dst + e4);
    float4 w4 = *(const float4*)(w   + e4);
    atomicAdd(&g_pack_out[s4.x], pack_deg(w4.x));
    atomicAdd(&g_pack_in [d4.x], pack_deg(w4.x));
    atomicAdd(&g_pack_out[s4.y], pack_deg(w4.y));
    atomicAdd(&g_pack_in [d4.y], pack_deg(w4.y));
    atomicAdd(&g_pack_out[s4.z], pack_deg(w4.z));
    atomicAdd(&g_pack_in [d4.z], pack_deg(w4.z));
    atomicAdd(&g_pack_out[s4.w], pack_deg(w4.w));
    atomicAdd(&g_pack_in [d4.w], pack_deg(w4.w));
}

// ---- scan stage 1 + node coefficients (fused; both node-wise) --------------
__global__ void scan1_kernel() {
    __shared__ int wsum[8];
    int b = blockIdx.x, t = threadIdx.x;       // 256 threads
    int base = b * SCAN_CHUNK;
    int local = 0;
    #pragma unroll
    for (int j = 0; j < 4; j++) {
        int i = t * 4 + j;
        if (i < SCAN_CHUNK) {
            int node = base + i;
            unsigned long long po = g_pack_out[node];
            unsigned long long pi = g_pack_in [node];
            float wo = (float)(unsigned)po * (1.0f / FIX_SCALE);
            float wi = (float)(unsigned)pi * (1.0f / FIX_SCALE);
            int co = (int)(po >> 32), ci = (int)(pi >> 32);
            g_r_out[node] = rsqrtf(fmaxf(wo, EPSW)) * rsqrtf(fmaxf((float)co, 1.0f));
            g_r_in [node] = rsqrtf(fmaxf(wi, EPSW)) * rsqrtf(fmaxf((float)ci, 1.0f));
            local += ci;
        }
    }
    int lane = t & 31, wid = t >> 5;
    #pragma unroll
    for (int off = 16; off > 0; off >>= 1)
        local += __shfl_down_sync(0xffffffff, local, off);
    if (lane == 0) wsum[wid] = local;
    __syncthreads();
    if (t == 0) {
        int s = 0;
        #pragma unroll
        for (int k = 0; k < 8; k++) s += wsum[k];
        g_blk_sum[b] = s;
    }
}

// ---- scan stage 2 (inline block-sum scan) + per-node exclusive scan --------
__global__ void scan3_kernel() {
    __shared__ int blk[SCAN_BLOCKS + 1];
    __shared__ int wsum[8];
    int b = blockIdx.x, t = threadIdx.x;       // 256 threads
    if (t == 0) {
        int run = 0;
        for (int k = 0; k < SCAN_BLOCKS; k++) {
            int c = g_blk_sum[k];
            blk[k] = run;
            run += c;
        }
        blk[SCAN_BLOCKS] = run;
    }
    __syncthreads();
    if (b == 0 && t == 0) g_row_start[N_NODES] = blk[SCAN_BLOCKS];

    int base = b * SCAN_CHUNK;
    int i0 = t * 4;
    int c0 = 0, c1 = 0, c2 = 0, c3 = 0;
    if (i0 < SCAN_CHUNK) {
        c0 = (int)(g_pack_in[base + i0]     >> 32);
        c1 = (int)(g_pack_in[base + i0 + 1] >> 32);
        c2 = (int)(g_pack_in[base + i0 + 2] >> 32);
        c3 = (int)(g_pack_in[base + i0 + 3] >> 32);
    }
    int s = c0 + c1 + c2 + c3;

    int lane = t & 31, wid = t >> 5;
    int incl = s;
    #pragma unroll
    for (int off = 1; off < 32; off <<= 1) {
        int n = __shfl_up_sync(0xffffffff, incl, off);
        if (lane >= off) incl += n;
    }
    if (lane == 31) wsum[wid] = incl;
    __syncthreads();
    int wpre = 0;
    #pragma unroll
    for (int k = 0; k < 8; k++) wpre += (k < wid) ? wsum[k] : 0;

    if (i0 < SCAN_CHUNK) {
        int run = blk[b] + wpre + (incl - s);
        g_row_start[base + i0]     = run;  g_cursor[base + i0]     = run;  run += c0;
        g_row_start[base + i0 + 1] = run;  g_cursor[base + i0 + 1] = run;  run += c1;
        g_row_start[base + i0 + 2] = run;  g_cursor[base + i0 + 2] = run;  run += c2;
        g_row_start[base + i0 + 3] = run;  g_cursor[base + i0 + 3] = run;
    }
}

// ---------------- scatter: x4 vectorized edge loads --------------------------
__global__ void scatter_kernel(const int* __restrict__ src,
                               const int* __restrict__ dst,
                               const float* __restrict__ w) {
    int e4 = (blockIdx.x * blockDim.x + threadIdx.x) * 4;
    if (e4 >= N_EDGES) return;
    int4   s4 = *(const int4*)  (src + e4);
    int4   d4 = *(const int4*)  (dst + e4);
    float4 w4 = *(const float4*)(w   + e4);

    float c0 = w4.x * g_r_out[s4.x] * g_r_in[d4.x];
    float c1 = w4.y * g_r_out[s4.y] * g_r_in[d4.y];
    float c2 = w4.z * g_r_out[s4.z] * g_r_in[d4.z];
    float c3 = w4.w * g_r_out[s4.w] * g_r_in[d4.w];

    int p0 = atomicAdd(&g_cursor[d4.x], 1);
    g_csr[p0] = make_int2(s4.x, __float_as_int(c0));
    int p1 = atomicAdd(&g_cursor[d4.y], 1);
    g_csr[p1] = make_int2(s4.y, __float_as_int(c1));
    int p2 = atomicAdd(&g_cursor[d4.z], 1);
    g_csr[p2] = make_int2(s4.z, __float_as_int(c2));
    int p3 = atomicAdd(&g_cursor[d4.w], 1);
    g_csr[p3] = make_int2(s4.w, __float_as_int(c3));
}

// ---------------- SpMM (CSR by dst, warp per node, fp16 gathers, 4-wide) -----
__global__ void spmm_csr_kernel(int layer) {
    int warp = (blockIdx.x * blockDim.x + threadIdx.x) >> 5;
    int lane = threadIdx.x & 31;
    if (warp >= N_NODES) return;

    const __half* feat = (layer == 0) ? g_x16 : g_h16;

    int beg = g_row_start[warp];
    int end = g_row_start[warp + 1];

    float acc0 = 0.f, acc1 = 0.f, acc2 = 0.f, acc3 = 0.f;
    int i = beg;
    for (; i + 3 < end; i += 4) {
        int2 p0 = g_csr[i];
        int2 p1 = g_csr[i + 1];
        int2 p2 = g_csr[i + 2];
        int2 p3 = g_csr[i + 3];
        uint2 v0 = *((const uint2*)(feat + (size_t)p0.x * F) + lane);
        uint2 v1 = *((const uint2*)(feat + (size_t)p1.x * F) + lane);
        uint2 v2 = *((const uint2*)(feat + (size_t)p2.x * F) + lane);
        uint2 v3 = *((const uint2*)(feat + (size_t)p3.x * F) + lane);
        float c0 = __int_as_float(p0.y), c1 = __int_as_float(p1.y);
        float c2 = __int_as_float(p2.y), c3 = __int_as_float(p3.y);
        {
            float2 a = __half22float2(*(__half2*)&v0.x);
            float2 b = __half22float2(*(__half2*)&v0.y);
            acc0 = fmaf(c0, a.x, acc0); acc1 = fmaf(c0, a.y, acc1);
            acc2 = fmaf(c0, b.x, acc2); acc3 = fmaf(c0, b.y, acc3);
        }
        {
            float2 a = __half22float2(*(__half2*)&v1.x);
            float2 b = __half22float2(*(__half2*)&v1.y);
            acc0 = fmaf(c1, a.x, acc0); acc1 = fmaf(c1, a.y, acc1);
            acc2 = fmaf(c1, b.x, acc2); acc3 = fmaf(c1, b.y, acc3);
        }
        {
            float2 a = __half22float2(*(__half2*)&v2.x);
            float2 b = __half22float2(*(__half2*)&v2.y);
            acc0 = fmaf(c2, a.x, acc0); acc1 = fmaf(c2, a.y, acc1);
            acc2 = fmaf(c2, b.x, acc2); acc3 = fmaf(c2, b.y, acc3);
        }
        {
            float2 a = __half22float2(*(__half2*)&v3.x);
            float2 b = __half22float2(*(__half2*)&v3.y);
            acc0 = fmaf(c3, a.x, acc0); acc1 = fmaf(c3, a.y, acc1);
            acc2 = fmaf(c3, b.x, acc2); acc3 = fmaf(c3, b.y, acc3);
        }
    }
    for (; i < end; i++) {
        int2 p = g_csr[i];
        float c = __int_as_float(p.y);
        uint2 v = *((const uint2*)(feat + (size_t)p.x * F) + lane);
        float2 a = __half22float2(*(__half2*)&v.x);
        float2 b = __half22float2(*(__half2*)&v.y);
        acc0 = fmaf(c, a.x, acc0); acc1 = fmaf(c, a.y, acc1);
        acc2 = fmaf(c, b.x, acc2); acc3 = fmaf(c, b.y, acc3);
    }
    float4 o = make_float4(acc0, acc1, acc2, acc3);
    *((float4*)(g_agg + (size_t)warp * F) + lane) = o;
}

// ---------------- mma.sync bf16 GEMM, 64-row M tile, 2 CTAs/SM ---------------
// 256 threads / 8 warps; warp tile 32(m) x 32(n); hi/lo split = 3 passes.
// SMEM: sA 64x264 + sB 128x264 bf16 = 101KB -> 2 CTAs/SM (load/epilogue of one
// CTA overlaps the other's MMA mainloop).
__global__ void __launch_bounds__(256, 2)
gemm_mma_kernel(const float* __restrict__ bias, float* __restrict__ outp, int layer) {
    extern __shared__ __nv_bfloat16 smem[];
    __nv_bfloat16* sA = smem;                          // [MTILE][ASTRIDE]
    __nv_bfloat16* sB = smem + MTILE * ASTRIDE;        // [128][ASTRIDE]

    int tid = threadIdx.x;
    int wid = tid >> 5, lane = tid & 31;
    int g = lane >> 2, tg = lane & 3;
    int bm = blockIdx.x * MTILE;
    int warp_m = (wid & 1) * 32;       // 2 m-groups cover 64 rows
    int warp_n = (wid >> 1) * 32;      // 4 n-groups cover 128 cols

    // ---- load + split A tile (agg rows, fp32 -> bf16 hi|lo along k) ----
    // 64 rows x 32 float4 = 2048 units / 256 threads = 8 iters
    #pragma unroll
    for (int it = 0; it < 8; it++) {
        int idx = it * 256 + tid;          // 0..2047
        int r  = idx >> 5;                 // 0..63
        int kq = (idx & 31) * 4;           // 0..124
        float4 v = make_float4(0.f, 0.f, 0.f, 0.f);
        if (bm + r < N_NODES)
            v = *(const float4*)(g_agg + (size_t)(bm + r) * F + kq);

        __nv_bfloat16 h0 = __float2bfloat16(v.x);
        __nv_bfloat16 h1 = __float2bfloat16(v.y);
        __nv_bfloat16 h2 = __float2bfloat16(v.z);
        __nv_bfloat16 h3 = __float2bfloat16(v.w);
        __nv_bfloat16 l0 = __float2bfloat16(v.x - __bfloat162float(h0));
        __nv_bfloat16 l1 = __float2bfloat16(v.y - __bfloat162float(h1));
        __nv_bfloat16 l2 = __float2bfloat16(v.z - __bfloat162float(h2));
        __nv_bfloat16 l3 = __float2bfloat16(v.w - __bfloat162float(h3));

        uint2 hi2, lo2;
        hi2.x = pack_bf16x2(h0, h1); hi2.y = pack_bf16x2(h2, h3);
        lo2.x = pack_bf16x2(l0, l1); lo2.y = pack_bf16x2(l2, l3);
        *(uint2*)(sA + r * ASTRIDE + kq)       = hi2;
        *(uint2*)(sA + r * ASTRIDE + 128 + kq) = lo2;
    }

    // ---- load B' tile (pre-split [n][256] bf16): 4096 uint4 / 256 = 16 iters
    const __nv_bfloat16* bp = g_bp + (size_t)layer * 32768;
    #pragma unroll
    for (int it = 0; it < 16; it++) {
        int idx = it * 256 + tid;          // 0..4095 uint4 units
        int n  = idx >> 5;                 // 0..127
        int kp = (idx & 31) * 8;           // 0..248
        *(uint4*)(sB + n * ASTRIDE + kp) = *(const uint4*)(bp + (size_t)n * 256 + kp);
    }
    __syncthreads();

    // ---- mainloop: 3 passes (hi*hi, lo*hi, hi*lo) x 8 k-steps x 8 mma -------
    float c[2][4][4];
    #pragma unroll
    for (int mt = 0; mt < 2; mt++)
        #pragma unroll
        for (int nt = 0; nt < 4; nt++)
            #pragma unroll
            for (int q = 0; q < 4; q++) c[mt][nt][q] = 0.0f;

    #pragma unroll
    for (int pass = 0; pass < 3; pass++) {
        int aoff = (pass == 1) ? 128 : 0;
        int boff = (pass == 2) ? 128 : 0;
        #pragma unroll
        for (int k0 = 0; k0 < 128; k0 += 16) {
            uint32_t a[2][4], b[4][2];
            #pragma unroll
            for (int mt = 0; mt < 2; mt++) {
                const __nv_bfloat16* base =
                    sA + (warp_m + mt * 16 + g) * ASTRIDE + aoff + k0 + 2 * tg;
                a[mt][0] = *(const uint32_t*)(base);
                a[mt][1] = *(const uint32_t*)(base + 8 * ASTRIDE);
                a[mt][2] = *(const uint32_t*)(base + 8);
                a[mt][3] = *(const uint32_t*)(base + 8 * ASTRIDE + 8);
            }
            #pragma unroll
            for (int nt = 0; nt < 4; nt++) {
                const __nv_bfloat16* base =
                    sB + (warp_n + nt * 8 + g) * ASTRIDE + boff + k0 + 2 * tg;
                b[nt][0] = *(const uint32_t*)(base);
                b[nt][1] = *(const uint32_t*)(base + 8);
            }
            #pragma unroll
            for (int mt = 0; mt < 2; mt++)
                #pragma unroll
                for (int nt = 0; nt < 4; nt++)
                    mma16816(c[mt][nt], a[mt], b[nt]);
        }
    }

    // ---- epilogue: bias + selu; layer 0 -> fp16 g_h16, layer 1 -> fp32 out --
    #pragma unroll
    for (int nt = 0; nt < 4; nt++) {
        int col = warp_n + nt * 8 + 2 * tg;
        float b0 = bias[col], b1 = bias[col + 1];
        #pragma unroll
        for (int mt = 0; mt < 2; mt++) {
            int row0 = bm + warp_m + mt * 16 + g;
            int row1 = row0 + 8;
            if (layer == 0) {
                if (row0 < N_NODES) {
                    __half2 o = __floats2half2_rn(selu_f(c[mt][nt][0] + b0),
                                                  selu_f(c[mt][nt][1] + b1));
                    *(__half2*)(g_h16 + (size_t)row0 * F + col) = o;
                }
                if (row1 < N_NODES) {
                    __half2 o = __floats2half2_rn(selu_f(c[mt][nt][2] + b0),
                                                  selu_f(c[mt][nt][3] + b1));
                    *(__half2*)(g_h16 + (size_t)row1 * F + col) = o;
                }
            } else {
                if (row0 < N_NODES) {
                    float2 o;
                    o.x = selu_f(c[mt][nt][0] + b0);
                    o.y = selu_f(c[mt][nt][1] + b1);
                    *(float2*)(outp + (size_t)row0 * F + col) = o;
                }
                if (row1 < N_NODES) {
                    float2 o;
                    o.x = selu_f(c[mt][nt][2] + b0);
                    o.y = selu_f(c[mt][nt][3] + b1);
                    *(float2*)(outp + (size_t)row1 * F + col) = o;
                }
            }
        }
    }
}

// ---------------- launch ------------------------------------------------------
extern "C" void kernel_launch(void* const* d_in, const int* in_sizes, int n_in,
                              void* d_out, int out_size) {
    const float* x   = (const float*)d_in[0];
    const int*   src = (const int*)  d_in[1];
    const int*   dst = (const int*)  d_in[2];
    const float* ew  = (const float*)d_in[3];
    const float* W1  = (const float*)d_in[4];
    const float* b1  = (const float*)d_in[5];
    const float* W2  = (const float*)d_in[6];
    const float* b2  = (const float*)d_in[7];
    float* out = (float*)d_out;

    const int TB = 256;
    dim3 setupGrid((N_NODES * F / 4 + TB - 1) / TB);
    dim3 edge4Grid((N_EDGES / 4 + TB - 1) / TB);
    dim3 spmmGrid(((size_t)N_NODES * 32 + TB - 1) / TB);
    dim3 gemmGrid((N_NODES + MTILE - 1) / MTILE);       // 782
    const int GEMM_SMEM = (MTILE + 128) * ASTRIDE * 2;  // 101376 B

    cudaFuncSetAttribute(gemm_mma_kernel,
                         cudaFuncAttributeMaxDynamicSharedMemorySize, GEMM_SMEM);

    // 0: setup (fp16 features + weight split + zero degree accumulators)
    setup_kernel<<<setupGrid, TB>>>(x, W1, W2);
    // 1: packed degrees (2 atomics/edge)
    deg_kernel<<<edge4Grid, TB>>>(src, dst, ew);
    // 2: block sums + node coefficients
    scan1_kernel<<<SCAN_BLOCKS, 256>>>();
    // 3: full exclusive scan -> row_start / cursor
    scan3_kernel<<<SCAN_BLOCKS, 256>>>();
    // 4: scatter edges into CSR
    scatter_kernel<<<edge4Grid, TB>>>(src, dst, ew);

    // 5-6: layer 1
    spmm_csr_kernel<<<spmmGrid, TB>>>(0);
    gemm_mma_kernel<<<gemmGrid, 256, GEMM_SMEM>>>(b1, out, 0);
    // 7-8: layer 2
    spmm_csr_kernel<<<spmmGrid, TB>>>(1);
    gemm_mma_kernel<<<gemmGrid, 256, GEMM_SMEM>>>(b2, out, 1);
}